// round 12
// baseline (speedup 1.0000x reference)
#include <cuda_runtime.h>
#include <cstdint>
#include <math.h>

#define NTHREADS 512
#define TMC      64
#define NCHUNK   8            // 256 k / 32
#define A_STRIDE 272          // 256 + 16 pad -> ldmatrix conflict-free
#define B_STRIDE 48           // 32 + 16 pad  -> ldmatrix conflict-free
#define A_PLANE  (TMC * A_STRIDE)     // 17408
#define B_PLANE  (256 * B_STRIDE)     // 12288
#define B_STAGE  (2 * B_PLANE)        // 24576

#define OFF_A1   0
#define OFF_A2   A_PLANE                    // 17408
#define OFF_B    (2 * A_PLANE)              // 34816 ; 2 stages
#define OFF_SA   (OFF_B + 2 * B_STAGE)      // 83968 ; 64 f (first holds rowmax bits)
#define OFF_QS   (OFF_SA + 256)             // 84224 ; 64 f
#define OFF_SB   (OFF_QS + 256)             // 84480 ; 256 f
#define OFF_B2S  (OFF_SB + 1024)            // 85504
#define OFF_W3S  (OFF_B2S + 1024)           // 86528
#define OFF_B3S  (OFF_W3S + 3072)           // 89600
#define OFF_RS   (OFF_B3S + 16)             // 89616
#define OFF_W1T  (OFF_RS + 768)             // 90384
#define OFF_B1T  (OFF_W1T + 3072)           // 93456
#define OFF_XS   (OFF_B1T + 1024)           // 94480
#define SMEM_BYTES (OFF_XS + 2304)          // 96784
#define OFF_PSUM OFF_B                      // epilogue reuse

// ---------------- global scratch: W2^T int8 2-split, [n][k] 256B rows -------
__device__ __align__(128) signed char g_w2q1[256 * 256];
__device__ __align__(128) signed char g_w2q2[256 * 256];
__device__ __align__(128) float       g_sb[256];

__device__ __forceinline__ uint32_t smem_u32(const void* p) {
    uint32_t a;
    asm("{ .reg .u64 t; cvta.to.shared.u64 t, %1; cvt.u32.u64 %0, t; }" : "=r"(a) : "l"(p));
    return a;
}

#define LDSM4(r, a)                                                           \
    asm volatile("ldmatrix.sync.aligned.m8n8.x4.shared.b16 {%0,%1,%2,%3}, [%4];" \
        : "=r"((r)[0]), "=r"((r)[1]), "=r"((r)[2]), "=r"((r)[3]) : "r"(a))

#define MMA_S8(acc, A, b0, b1)                                                \
    asm volatile(                                                             \
        "mma.sync.aligned.m16n8k32.row.col.s32.s8.s8.s32 "                    \
        "{%0,%1,%2,%3}, {%4,%5,%6,%7}, {%8,%9}, {%0,%1,%2,%3};"               \
        : "+r"((acc)[0]), "+r"((acc)[1]), "+r"((acc)[2]), "+r"((acc)[3])      \
        : "r"((A)[0]), "r"((A)[1]), "r"((A)[2]), "r"((A)[3]),                 \
          "r"(b0), "r"(b1))

#define CP_ASYNC16(dst, src)                                                  \
    asm volatile("cp.async.cg.shared.global [%0], [%1], 16;" :: "r"(dst), "l"(src) : "memory")
#define CP_COMMIT()  asm volatile("cp.async.commit_group;" ::: "memory")
#define CP_WAIT0()   asm volatile("cp.async.wait_group 0;" ::: "memory")

// ---------------- kernel 1: per-column int8 2-split of W2 -------------------
__global__ void prep_w2(const float* __restrict__ W2) {
    __shared__ float red[256];
    int n = blockIdx.x;
    int k = threadIdx.x;
    float v = W2[k * 256 + n];
    red[k] = fabsf(v);
    __syncthreads();
    for (int s = 128; s > 0; s >>= 1) {
        if (k < s) red[k] = fmaxf(red[k], red[k + s]);
        __syncthreads();
    }
    float mx = fmaxf(red[0], 1e-20f);
    if (k == 0) g_sb[n] = mx / 127.f;
    float u  = v * (127.f / mx);
    float q1 = rintf(u);
    int   q2 = (int)rintf((u - q1) * 256.f);
    q2 = q2 > 127 ? 127 : (q2 < -128 ? -128 : q2);
    g_w2q1[n * 256 + k] = (signed char)q1;
    g_w2q2[n * 256 + k] = (signed char)q2;
}

// issue B chunk c (both planes) into buffer buf; 2 cp.async per thread
__device__ __forceinline__ void issue_b(uint32_t sb, int c, int buf, int tid) {
    int n = tid >> 1, seg = tid & 1;
    uint32_t d = sb + OFF_B + (uint32_t)buf * B_STAGE + n * B_STRIDE + seg * 16;
    const char* s1 = (const char*)g_w2q1 + n * 256 + c * 32 + seg * 16;
    const char* s2 = (const char*)g_w2q2 + n * 256 + c * 32 + seg * 16;
    CP_ASYNC16(d, s1);
    CP_ASYNC16(d + B_PLANE, s2);
}

// ---------------- kernel 2: fused main ----------------
__global__ __launch_bounds__(NTHREADS, 1)
void nn_adiab_imma(const float* __restrict__ x,
                   const float* __restrict__ W1,
                   const float* __restrict__ b1,
                   const float* __restrict__ b2,
                   const float* __restrict__ W3,
                   const float* __restrict__ b3,
                   float* __restrict__ out,
                   int B)
{
    extern __shared__ __align__(128) char smem[];
    const uint32_t sb = smem_u32(smem);
    const int tid  = threadIdx.x;
    const int wid  = tid >> 5;
    const int lane = tid & 31;
    const int g    = lane >> 2;
    const int t    = lane & 3;
    const int wy   = wid & 1;        // 2 m-warps x 32 rows
    const int wx   = wid >> 1;       // 8 n-warps x 32 cols
    const int m0w  = wy * 32;
    const int n0w  = wx * 32;
    const int row0 = blockIdx.x * TMC;

    // ---- prefetch B chunk 0 into buf 0 ----
    issue_b(sb, 0, 0, tid);
    CP_COMMIT();

    float* sAs = (float*)(smem + OFF_SA);
    int*   rmI = (int*)(smem + OFF_SA);     // rowmax bits (pre-scale)
    float* qss = (float*)(smem + OFF_QS);
    float* sBs = (float*)(smem + OFF_SB);
    float* b2s = (float*)(smem + OFF_B2S);
    float* w3s = (float*)(smem + OFF_W3S);
    float* b3s = (float*)(smem + OFF_B3S);
    float* rs  = (float*)(smem + OFF_RS);
    float* w1s = (float*)(smem + OFF_W1T);
    float* b1s = (float*)(smem + OFF_B1T);
    float* xs  = (float*)(smem + OFF_XS);

    for (int i = tid; i < 768; i += NTHREADS) w1s[i] = W1[i];
    for (int i = tid; i < 256; i += NTHREADS) { b1s[i] = b1[i]; b2s[i] = b2[i]; sBs[i] = g_sb[i]; }
    for (int i = tid; i < 768; i += NTHREADS) w3s[i] = W3[i];
    if (tid < 3) b3s[tid] = b3[tid];
    if (tid < TMC) rmI[tid] = 0;
    for (int i = tid; i < TMC * 9; i += NTHREADS) {
        int r = row0 + i / 9;
        xs[i] = (r < B) ? x[(size_t)row0 * 9 + i] : 0.f;
    }
    __syncthreads();

    // ---- pairwise distances ----
    if (tid < TMC) {
        const float* p = xs + tid * 9;
        float ax=p[0],ay=p[1],az=p[2], bx=p[3],by=p[4],bz=p[5], cx=p[6],cy=p[7],cz=p[8];
        float d0x=ax-bx, d0y=ay-by, d0z=az-bz;
        float d1x=ax-cx, d1y=ay-cy, d1z=az-cz;
        float d2x=bx-cx, d2y=by-cy, d2z=bz-cz;
        rs[tid*3+0] = sqrtf(d0x*d0x + d0y*d0y + d0z*d0z);
        rs[tid*3+1] = sqrtf(d1x*d1x + d1y*d1y + d1z*d1z);
        rs[tid*3+2] = sqrtf(d2x*d2x + d2y*d2y + d2z*d2z);
    }
    __syncthreads();

    // ---- layer 1 + row max (values kept in registers) ----
    // thread handles 16 kpairs: flat = i*512+tid; m = flat>>7; kp = flat&127
    // all lanes of a warp share m at each i.
    float hv[32];
    {
        float vmax = 0.f;
        int curm = -1;
        #pragma unroll
        for (int i = 0; i < 16; i++) {
            int flat = i * NTHREADS + tid;
            int m  = flat >> 7;
            int kp = flat & 127;
            int k  = kp * 2;
            float r0 = rs[m*3+0], r1 = rs[m*3+1], r2 = rs[m*3+2];
            float v0 = fmaf(r0, w1s[k],   fmaf(r1, w1s[256+k],   fmaf(r2, w1s[512+k],   b1s[k])));
            float v1 = fmaf(r0, w1s[k+1], fmaf(r1, w1s[256+k+1], fmaf(r2, w1s[512+k+1], b1s[k+1])));
            v0 = fmaxf(v0, 0.f);
            v1 = fmaxf(v1, 0.f);
            hv[2*i] = v0; hv[2*i+1] = v1;
            float vm = fmaxf(v0, v1);
            if (m != curm) {        // new row for this thread's sequence: flush prev
                if (curm >= 0) {
                    #pragma unroll
                    for (int off = 16; off > 0; off >>= 1)
                        vmax = fmaxf(vmax, __shfl_xor_sync(0xffffffffu, vmax, off));
                    if (lane == 0) atomicMax(&rmI[curm], __float_as_int(vmax));
                }
                curm = m; vmax = vm;
            } else vmax = fmaxf(vmax, vm);
        }
        #pragma unroll
        for (int off = 16; off > 0; off >>= 1)
            vmax = fmaxf(vmax, __shfl_xor_sync(0xffffffffu, vmax, off));
        if (lane == 0) atomicMax(&rmI[curm], __float_as_int(vmax));
    }
    __syncthreads();
    if (tid < TMC) {
        float mx = fmaxf(__int_as_float(rmI[tid]), 1e-20f);
        float sA = mx / 127.f;
        float qs = 127.f / mx;
        sAs[tid] = sA;          // overwrites rowmax bits
        qss[tid] = qs;
    }
    __syncthreads();

    // ---- quantize A into smem planes ----
    #pragma unroll
    for (int i = 0; i < 16; i++) {
        int flat = i * NTHREADS + tid;
        int m  = flat >> 7;
        int kp = flat & 127;
        float qs = qss[m];
        float u0 = hv[2*i]   * qs;
        float u1 = hv[2*i+1] * qs;
        float p0 = rintf(u0), p1 = rintf(u1);
        int q20 = (int)rintf((u0 - p0) * 256.f);
        int q21 = (int)rintf((u1 - p1) * 256.f);
        q20 = q20 > 127 ? 127 : (q20 < -128 ? -128 : q20);
        q21 = q21 > 127 ? 127 : (q21 < -128 ? -128 : q21);
        int i0 = (int)p0, i1 = (int)p1;
        unsigned short pk1 = (unsigned short)((i0 & 0xFF) | ((i1 & 0xFF) << 8));
        unsigned short pk2 = (unsigned short)((q20 & 0xFF) | ((q21 & 0xFF) << 8));
        uint32_t off = (uint32_t)m * A_STRIDE + (uint32_t)kp * 2;
        *(unsigned short*)(smem + OFF_A1 + off) = pk1;
        *(unsigned short*)(smem + OFF_A2 + off) = pk2;
    }
    __syncthreads();

    // ---- per-thread ldmatrix offsets (byte-identical to f16-k16 mapping) ----
    const int jj = lane >> 3, rr = lane & 7;
    const uint32_t aoffA = (uint32_t)(m0w + ((jj & 1) << 3) + rr) * A_STRIDE
                         + ((uint32_t)(jj >> 1) << 4);
    const uint32_t boffB = (uint32_t)(n0w + ((jj >> 1) << 3) + rr) * B_STRIDE
                         + ((uint32_t)(jj & 1) << 4);

    // ---- accumulators: acc1 = A1B1, acc2 = A1B2 + A2B1 ----
    int acc1[2][4][4], acc2[2][4][4];
    #pragma unroll
    for (int mt = 0; mt < 2; mt++)
        #pragma unroll
        for (int q = 0; q < 4; q++)
            #pragma unroll
            for (int e = 0; e < 4; e++) { acc1[mt][q][e] = 0; acc2[mt][q][e] = 0; }

    // ---- mainloop: 8 chunks of k=32, 2-stage B ----
    for (int c = 0; c < NCHUNK; c++) {
        const int buf = c & 1;
        CP_WAIT0();
        __syncthreads();
        if (c + 1 < NCHUNK) issue_b(sb, c + 1, buf ^ 1, tid);
        CP_COMMIT();

        uint32_t a1f[2][4], a2f[2][4];
        const uint32_t ka = aoffA + (uint32_t)c * 32;
        LDSM4(a1f[0], sb + OFF_A1 + ka);
        LDSM4(a1f[1], sb + OFF_A1 + ka + 16 * A_STRIDE);
        LDSM4(a2f[0], sb + OFF_A2 + ka);
        LDSM4(a2f[1], sb + OFF_A2 + ka + 16 * A_STRIDE);

        const uint32_t bb = sb + OFF_B + (uint32_t)buf * B_STAGE + boffB;
        uint32_t b1f[8], b2f[8];
        LDSM4(b1f,     bb);
        LDSM4(b1f + 4, bb + 2 * (8 * B_STRIDE));
        LDSM4(b2f,     bb + B_PLANE);
        LDSM4(b2f + 4, bb + B_PLANE + 2 * (8 * B_STRIDE));

        #pragma unroll
        for (int mt = 0; mt < 2; mt++)
            #pragma unroll
            for (int q = 0; q < 4; q++)
                MMA_S8(acc1[mt][q], a1f[mt], b1f[2*q], b1f[2*q+1]);
        #pragma unroll
        for (int mt = 0; mt < 2; mt++)
            #pragma unroll
            for (int q = 0; q < 4; q++)
                MMA_S8(acc2[mt][q], a1f[mt], b2f[2*q], b2f[2*q+1]);
        #pragma unroll
        for (int mt = 0; mt < 2; mt++)
            #pragma unroll
            for (int q = 0; q < 4; q++)
                MMA_S8(acc2[mt][q], a2f[mt], b1f[2*q], b1f[2*q+1]);
    }

    // ---- epilogue: dequant + bias2 + relu + layer3 partials ----
    __syncthreads();
    float* psum = (float*)(smem + OFF_PSUM);   // [8 wx][64 row][3]
    const float c256 = 1.f / 256.f;
    #pragma unroll
    for (int mt = 0; mt < 2; mt++) {
        const int r0l = m0w + mt * 16 + g;
        const float sa0 = sAs[r0l], sa1 = sAs[r0l + 8];
        float p[2][3];
        p[0][0]=p[0][1]=p[0][2]=0.f;
        p[1][0]=p[1][1]=p[1][2]=0.f;
        #pragma unroll
        for (int nt = 0; nt < 4; nt++) {
            int n  = n0w + nt * 8 + 2 * t;
            int n2 = n + 1;
            float sbn = sBs[n], sbn2 = sBs[n2];
            float z00 = sa0 * sbn  * fmaf((float)acc2[mt][nt][0], c256, (float)acc1[mt][nt][0]);
            float z01 = sa0 * sbn2 * fmaf((float)acc2[mt][nt][1], c256, (float)acc1[mt][nt][1]);
            float z10 = sa1 * sbn  * fmaf((float)acc2[mt][nt][2], c256, (float)acc1[mt][nt][2]);
            float z11 = sa1 * sbn2 * fmaf((float)acc2[mt][nt][3], c256, (float)acc1[mt][nt][3]);
            float h00 = fmaxf(z00 + b2s[n],  0.f);
            float h01 = fmaxf(z01 + b2s[n2], 0.f);
            float h10 = fmaxf(z10 + b2s[n],  0.f);
            float h11 = fmaxf(z11 + b2s[n2], 0.f);
            #pragma unroll
            for (int j = 0; j < 3; j++) {
                float wA = w3s[n * 3 + j], wB = w3s[n2 * 3 + j];
                p[0][j] = fmaf(h00, wA, fmaf(h01, wB, p[0][j]));
                p[1][j] = fmaf(h10, wA, fmaf(h11, wB, p[1][j]));
            }
        }
        #pragma unroll
        for (int s = 0; s < 2; s++)
            #pragma unroll
            for (int j = 0; j < 3; j++) {
                p[s][j] += __shfl_xor_sync(0xffffffffu, p[s][j], 1);
                p[s][j] += __shfl_xor_sync(0xffffffffu, p[s][j], 2);
            }
        if (t == 0) {
            #pragma unroll
            for (int s = 0; s < 2; s++) {
                int rloc = r0l + 8 * s;
                #pragma unroll
                for (int j = 0; j < 3; j++)
                    psum[(wx * TMC + rloc) * 3 + j] = p[s][j];
            }
        }
    }
    __syncthreads();

    // ---- final cross-warp reduce + eigen + store ----
    if (tid < TMC) {
        int gr = row0 + tid;
        if (gr < B) {
            float w0 = b3s[0], w1 = b3s[1], w2 = b3s[2];
            #pragma unroll
            for (int q = 0; q < 8; q++) {
                w0 += psum[(q * TMC + tid) * 3 + 0];
                w1 += psum[(q * TMC + tid) * 3 + 1];
                w2 += psum[(q * TMC + tid) * 3 + 2];
            }
            float mean = 0.5f * (w0 + w1);
            float dd   = 0.5f * (w0 - w1);
            float rad  = sqrtf(dd * dd + w2 * w2);
            out[(size_t)gr * 2 + 0] = mean - rad;
            out[(size_t)gr * 2 + 1] = mean + rad;
        }
    }
}

extern "C" void kernel_launch(void* const* d_in, const int* in_sizes, int n_in,
                              void* d_out, int out_size)
{
    const float* x  = (const float*)d_in[0];
    const float* W1 = (const float*)d_in[1];
    const float* b1 = (const float*)d_in[2];
    const float* W2 = (const float*)d_in[3];
    const float* b2 = (const float*)d_in[4];
    const float* W3 = (const float*)d_in[5];
    const float* b3 = (const float*)d_in[6];
    float* out = (float*)d_out;

    int B = in_sizes[0] / 9;
    int grid = (B + TMC - 1) / TMC;

    prep_w2<<<256, 256>>>(W2);

    cudaFuncSetAttribute(nn_adiab_imma,
                         cudaFuncAttributeMaxDynamicSharedMemorySize, SMEM_BYTES);
    nn_adiab_imma<<<grid, NTHREADS, SMEM_BYTES>>>(x, W1, b1, b2, W3, b3, out, B);
}

// round 16
// speedup vs baseline: 2.6473x; 2.6473x over previous
#include <cuda_runtime.h>
#include <cuda_fp16.h>
#include <cstdint>
#include <math.h>

#define NTHREADS 512
#define TM       128
#define NCHUNK   8           // 256 k / 32
#define KCH      32
#define A_STRIDE 528         // 512 + 16 pad -> ldmatrix conflict-free
#define B_STRIDE 80          // 64 + 16 pad  -> ldmatrix conflict-free
#define A_MAT    (TM * A_STRIDE)      // 67584
#define B_MAT    (256 * B_STRIDE)     // 20480

#define OFF_AHI  0
#define OFF_ALO  A_MAT                        // 67584
#define OFF_B0   (2 * A_MAT)                  // 135168  [2 buf][2 mat] * B_MAT
#define OFF_B2S  (OFF_B0 + 4 * B_MAT)         // 217088
#define OFF_W3S  (OFF_B2S + 1024)             // 218112
#define OFF_B3S  (OFF_W3S + 3072)             // 221184
#define OFF_RS   (OFF_B3S + 16)               // 221200
#define SMEM_BYTES (OFF_RS + 1536)            // 222736 (<= 227KB, 1 CTA/SM)
// transient regions (inside B buf1, free until chunk 1 is issued):
#define OFF_W1T  (OFF_B0 + 2 * B_MAT)         // 176128
#define OFF_B1T  (OFF_W1T + 3072)
#define OFF_XS   (OFF_B1T + 1024)
// epilogue psum reuses B buf0 region:
#define OFF_PSUM OFF_B0

// ---------------- global scratch: W2^T split fp16 hi/lo, [n][k] 512B rows ----
__device__ __align__(128) __half g_w2t_hi[256 * 256];
__device__ __align__(128) __half g_w2t_lo[256 * 256];

__device__ __forceinline__ uint32_t smem_u32(const void* p) {
    uint32_t a;
    asm("{ .reg .u64 t; cvta.to.shared.u64 t, %1; cvt.u32.u64 %0, t; }" : "=r"(a) : "l"(p));
    return a;
}

#define LDSM4(r, a)                                                           \
    asm volatile("ldmatrix.sync.aligned.m8n8.x4.shared.b16 {%0,%1,%2,%3}, [%4];" \
        : "=r"((r)[0]), "=r"((r)[1]), "=r"((r)[2]), "=r"((r)[3]) : "r"(a))

#define MMA_F16(acc, A, b0, b1)                                               \
    asm volatile(                                                             \
        "mma.sync.aligned.m16n8k16.row.col.f32.f16.f16.f32 "                  \
        "{%0,%1,%2,%3}, {%4,%5,%6,%7}, {%8,%9}, {%0,%1,%2,%3};"               \
        : "+f"((acc)[0]), "+f"((acc)[1]), "+f"((acc)[2]), "+f"((acc)[3])      \
        : "r"((A)[0]), "r"((A)[1]), "r"((A)[2]), "r"((A)[3]),                 \
          "r"(b0), "r"(b1))

#define CP_ASYNC16(dst, src)                                                  \
    asm volatile("cp.async.cg.shared.global [%0], [%1], 16;" :: "r"(dst), "l"(src) : "memory")
#define CP_COMMIT()  asm volatile("cp.async.commit_group;" ::: "memory")
#define CP_WAIT0()   asm volatile("cp.async.wait_group 0;" ::: "memory")

// ---------------- kernel 1: transpose + split W2 -> fp16 hi/lo [n][k] -------
__global__ void prep_w2(const float* __restrict__ W2) {
    __shared__ float tile[32][33];
    int bx = blockIdx.x & 7;        // n tile
    int by = blockIdx.x >> 3;       // k tile
    int tx = threadIdx.x & 31;
    int ty = threadIdx.x >> 5;
    #pragma unroll
    for (int i = 0; i < 32; i += 8)
        tile[ty + i][tx] = W2[(by * 32 + ty + i) * 256 + bx * 32 + tx];
    __syncthreads();
    #pragma unroll
    for (int i = 0; i < 32; i += 8) {
        int n = bx * 32 + ty + i;
        int k = by * 32 + tx;
        float v = tile[tx][ty + i];                 // W2[k][n]
        __half h = __float2half_rn(v);
        g_w2t_hi[n * 256 + k] = h;
        g_w2t_lo[n * 256 + k] = __float2half_rn(v - __half2float(h));
    }
}

// issue one B chunk (32 k-cols of hi+lo) into buffer `buf`
__device__ __forceinline__ void issue_b_chunk(uint32_t sb, const char* ghi,
                                              const char* glo, int c, int buf, int tid)
{
    #pragma unroll
    for (int u = 0; u < 4; u++) {
        int gi  = u * NTHREADS + tid;     // 0..2047
        int mat = gi >> 10;
        int wi  = gi & 1023;
        int n   = wi >> 2;
        int seg = wi & 3;
        uint32_t dst = sb + OFF_B0 + (buf * 2 + mat) * B_MAT + n * B_STRIDE + seg * 16;
        CP_ASYNC16(dst, (mat ? glo : ghi) + n * 512 + c * 64 + seg * 16);
    }
    CP_COMMIT();
}

// ---------------- kernel 2: fused main ----------------
__global__ __launch_bounds__(NTHREADS, 1)
void nn_adiab_mma(const float* __restrict__ x,
                  const float* __restrict__ W1,
                  const float* __restrict__ b1,
                  const float* __restrict__ b2,
                  const float* __restrict__ W3,
                  const float* __restrict__ b3,
                  float* __restrict__ out,
                  int B)
{
    extern __shared__ __align__(128) char smem[];
    const uint32_t sb = smem_u32(smem);
    const int tid  = threadIdx.x;
    const int wid  = tid >> 5;
    const int lane = tid & 31;
    const int g    = lane >> 2;
    const int t    = lane & 3;
    const int wy   = wid & 3;        // 4 m-warps x 32 rows
    const int wx   = wid >> 2;       // 4 n-warps x 64 cols
    const int m0w  = wy * 32;
    const int n0w  = wx * 64;
    const int row0 = blockIdx.x * TM;

    const char* ghi = (const char*)g_w2t_hi;
    const char* glo = (const char*)g_w2t_lo;

    // ---- prefetch B chunk 0 into buf 0 immediately ----
    issue_b_chunk(sb, ghi, glo, 0, 0, tid);

    // ---- transient loads (live in B buf1 region until chunk 1 issued) ----
    float* w1s = (float*)(smem + OFF_W1T);
    float* b1s = (float*)(smem + OFF_B1T);
    float* xs  = (float*)(smem + OFF_XS);
    float* b2s = (float*)(smem + OFF_B2S);
    float* w3s = (float*)(smem + OFF_W3S);
    float* b3s = (float*)(smem + OFF_B3S);
    float* rs  = (float*)(smem + OFF_RS);

    for (int i = tid; i < 768; i += NTHREADS) w1s[i] = W1[i];
    for (int i = tid; i < 256; i += NTHREADS) { b1s[i] = b1[i]; b2s[i] = b2[i]; }
    for (int i = tid; i < 768; i += NTHREADS) w3s[i] = W3[i];
    if (tid < 3) b3s[tid] = b3[tid];
    for (int i = tid; i < TM * 9; i += NTHREADS) {
        int r = row0 + i / 9;
        xs[i] = (r < B) ? x[(size_t)row0 * 9 + i] : 0.f;
    }
    __syncthreads();

    // ---- pairwise distances ----
    if (tid < TM) {
        const float* p = xs + tid * 9;
        float ax=p[0],ay=p[1],az=p[2], bx=p[3],by=p[4],bz=p[5], cx=p[6],cy=p[7],cz=p[8];
        float d0x=ax-bx, d0y=ay-by, d0z=az-bz;
        float d1x=ax-cx, d1y=ay-cy, d1z=az-cz;
        float d2x=bx-cx, d2y=by-cy, d2z=bz-cz;
        rs[tid*3+0] = sqrtf(d0x*d0x + d0y*d0y + d0z*d0z);
        rs[tid*3+1] = sqrtf(d1x*d1x + d1y*d1y + d1z*d1z);
        rs[tid*3+2] = sqrtf(d2x*d2x + d2y*d2y + d2z*d2z);
    }
    __syncthreads();

    // ---- build FULL A = split-fp16(h1): [128 m][256 k], hi/lo, ONCE ----
    #pragma unroll 4
    for (int i = 0; i < 32; i++) {
        int flat = i * NTHREADS + tid;
        int m  = flat >> 7;
        int kp = flat & 127;
        int k  = kp * 2;
        float r0 = rs[m*3+0], r1 = rs[m*3+1], r2 = rs[m*3+2];
        float v0 = fmaf(r0, w1s[k],   fmaf(r1, w1s[256+k],   fmaf(r2, w1s[512+k],   b1s[k])));
        float v1 = fmaf(r0, w1s[k+1], fmaf(r1, w1s[256+k+1], fmaf(r2, w1s[512+k+1], b1s[k+1])));
        v0 = fmaxf(v0, 0.f);
        v1 = fmaxf(v1, 0.f);
        __half2 hp = __floats2half2_rn(v0, v1);
        float h0f = __half2float(__low2half(hp));
        float h1f = __half2float(__high2half(hp));
        __half2 lp = __floats2half2_rn(v0 - h0f, v1 - h1f);
        uint32_t off = (uint32_t)m * A_STRIDE + (uint32_t)k * 2;
        *(uint32_t*)(smem + OFF_AHI + off) = *(uint32_t*)&hp;
        *(uint32_t*)(smem + OFF_ALO + off) = *(uint32_t*)&lp;
    }
    __syncthreads();     // A done; w1s/b1s/xs dead -> buf1 free

    // ---- per-thread ldmatrix offsets ----
    const int jj = lane >> 3, rr = lane & 7;
    const int mOff  = ((jj & 1) << 3) + rr;
    const int kOffA = ((jj >> 1) << 3) * 2;          // 0 or 16 B
    const uint32_t aoffA = (uint32_t)(m0w + mOff) * A_STRIDE + kOffA;
    const int nOffB = ((jj >> 1) << 3) + rr;
    const int kOffB = ((jj & 1) << 3) * 2;           // 0 or 16 B
    const uint32_t boffB = (uint32_t)(n0w + nOffB) * B_STRIDE + kOffB;

    // ---- accumulators ----
    float acc[2][8][4];
    #pragma unroll
    for (int mt = 0; mt < 2; mt++)
        #pragma unroll
        for (int nt = 0; nt < 8; nt++)
            #pragma unroll
            for (int q = 0; q < 4; q++) acc[mt][nt][q] = 0.f;

    // ---- mainloop: 8 chunks of k=32, 2-stage B double buffer ----
    for (int c = 0; c < NCHUNK; c++) {
        const int buf = c & 1;
        CP_WAIT0();              // chunk c arrived
        __syncthreads();         // ...and prior-stage reads retired
        if (c + 1 < NCHUNK)
            issue_b_chunk(sb, ghi, glo, c + 1, buf ^ 1, tid);

        // ---- hoist ALL A fragments for both kt sub-steps (8 LDSM) ----
        // kt=1's loads drain while kt=0's MMAs execute.
        uint32_t ah[2][2][4], al[2][2][4];       // [kt][mt][frag]
        #pragma unroll
        for (int kt = 0; kt < 2; kt++) {
            const uint32_t ka = aoffA + (uint32_t)(c * 32 + kt * 16) * 2;
            LDSM4(ah[kt][0], sb + OFF_AHI + ka);
            LDSM4(ah[kt][1], sb + OFF_AHI + ka + 16 * A_STRIDE);
            LDSM4(al[kt][0], sb + OFF_ALO + ka);
            LDSM4(al[kt][1], sb + OFF_ALO + ka + 16 * A_STRIDE);
        }

        #pragma unroll
        for (int kt = 0; kt < 2; kt++) {
            const uint32_t bb = sb + OFF_B0 + (buf * 2) * B_MAT + boffB + kt * 32;
            #pragma unroll
            for (int h = 0; h < 2; h++) {
                uint32_t bh[8], bl[8];
                LDSM4(bh,     bb + (h * 4 + 0) * (8 * B_STRIDE));
                LDSM4(bh + 4, bb + (h * 4 + 2) * (8 * B_STRIDE));
                LDSM4(bl,     bb + B_MAT + (h * 4 + 0) * (8 * B_STRIDE));
                LDSM4(bl + 4, bb + B_MAT + (h * 4 + 2) * (8 * B_STRIDE));
                #pragma unroll
                for (int mt = 0; mt < 2; mt++)
                    #pragma unroll
                    for (int q = 0; q < 4; q++)
                        MMA_F16(acc[mt][h * 4 + q], ah[kt][mt], bh[2 * q], bh[2 * q + 1]);
                #pragma unroll
                for (int mt = 0; mt < 2; mt++)
                    #pragma unroll
                    for (int q = 0; q < 4; q++)
                        MMA_F16(acc[mt][h * 4 + q], al[kt][mt], bh[2 * q], bh[2 * q + 1]);
                #pragma unroll
                for (int mt = 0; mt < 2; mt++)
                    #pragma unroll
                    for (int q = 0; q < 4; q++)
                        MMA_F16(acc[mt][h * 4 + q], ah[kt][mt], bl[2 * q], bl[2 * q + 1]);
            }
        }
    }

    // ---- epilogue: bias2 + relu + layer3 partials ----
    __syncthreads();
    float* psum = (float*)(smem + OFF_PSUM);   // [4 wx][128 row][3]
    #pragma unroll
    for (int mt = 0; mt < 2; mt++) {
        float p[2][3];
        p[0][0]=p[0][1]=p[0][2]=0.f;
        p[1][0]=p[1][1]=p[1][2]=0.f;
        #pragma unroll
        for (int nt = 0; nt < 8; nt++) {
            int n  = n0w + nt * 8 + 2 * t;
            int n2 = n + 1;
            float bn = b2s[n], bn2 = b2s[n2];
            float h00 = fmaxf(acc[mt][nt][0] + bn,  0.f);
            float h01 = fmaxf(acc[mt][nt][1] + bn2, 0.f);
            float h10 = fmaxf(acc[mt][nt][2] + bn,  0.f);
            float h11 = fmaxf(acc[mt][nt][3] + bn2, 0.f);
            #pragma unroll
            for (int j = 0; j < 3; j++) {
                float wA = w3s[n * 3 + j], wB = w3s[n2 * 3 + j];
                p[0][j] = fmaf(h00, wA, fmaf(h01, wB, p[0][j]));
                p[1][j] = fmaf(h10, wA, fmaf(h11, wB, p[1][j]));
            }
        }
        #pragma unroll
        for (int s = 0; s < 2; s++)
            #pragma unroll
            for (int j = 0; j < 3; j++) {
                p[s][j] += __shfl_xor_sync(0xffffffffu, p[s][j], 1);
                p[s][j] += __shfl_xor_sync(0xffffffffu, p[s][j], 2);
            }
        if (t == 0) {
            #pragma unroll
            for (int s = 0; s < 2; s++) {
                int rloc = m0w + mt * 16 + g + 8 * s;
                #pragma unroll
                for (int j = 0; j < 3; j++)
                    psum[(wx * TM + rloc) * 3 + j] = p[s][j];
            }
        }
    }
    __syncthreads();

    // ---- final cross-warp reduce + eigen + store ----
    if (tid < TM) {
        int gr = row0 + tid;
        if (gr < B) {
            float w0 = b3s[0], w1 = b3s[1], w2 = b3s[2];
            #pragma unroll
            for (int q = 0; q < 4; q++) {
                w0 += psum[(q * TM + tid) * 3 + 0];
                w1 += psum[(q * TM + tid) * 3 + 1];
                w2 += psum[(q * TM + tid) * 3 + 2];
            }
            float mean = 0.5f * (w0 + w1);
            float dd   = 0.5f * (w0 - w1);
            float rad  = sqrtf(dd * dd + w2 * w2);
            out[(size_t)gr * 2 + 0] = mean - rad;
            out[(size_t)gr * 2 + 1] = mean + rad;
        }
    }
}

extern "C" void kernel_launch(void* const* d_in, const int* in_sizes, int n_in,
                              void* d_out, int out_size)
{
    const float* x  = (const float*)d_in[0];
    const float* W1 = (const float*)d_in[1];
    const float* b1 = (const float*)d_in[2];
    const float* W2 = (const float*)d_in[3];
    const float* b2 = (const float*)d_in[4];
    const float* W3 = (const float*)d_in[5];
    const float* b3 = (const float*)d_in[6];
    float* out = (float*)d_out;

    int B = in_sizes[0] / 9;
    int grid = (B + TM - 1) / TM;

    prep_w2<<<64, 256>>>(W2);

    cudaFuncSetAttribute(nn_adiab_mma,
                         cudaFuncAttributeMaxDynamicSharedMemorySize, SMEM_BYTES);
    nn_adiab_mma<<<grid, NTHREADS, SMEM_BYTES>>>(x, W1, b1, b2, W3, b3, out, B);
}